// round 1
// baseline (speedup 1.0000x reference)
#include <cuda_runtime.h>
#include <math.h>
#include <stdint.h>

#define D      768
#define SLEN   2048
#define BATCH  32
#define CHUNKS 16
#define TILE   32
#define NTILE  4      // chunk = NTILE*TILE = 128 s-positions
#define NTHR   256

// ---------------- scratch (single device symbol, no allocations) ----------------
// layout (floats):
//   pa_lin   [32*768]      @ 0
//   pa       [32*768]      @ 24576
//   xcq      [32*2304]     @ 49152
//   cq_lin   [32*768]      @ 122880
//   u        [32*768]      @ 147456
//   logits   [32*2048]     @ 172032
//   mpart    [32*16*3]     @ 237568
//   lpart    [32*16*3]     @ 239104
//   accpart  [32*16*3*768] @ 240640
//   mfin     [32*3]        @ 1420288
//   lfin     [32*3]        @ 1420384
//   xfuse    [64*1536]     @ 1420480
//   ctrl_lin [64*768]      @ 1518784
__device__ float g_scratch[1568000];

#define OFF_PA_LIN   0
#define OFF_PA       24576
#define OFF_XCQ      49152
#define OFF_CQ_LIN   122880
#define OFF_U        147456
#define OFF_LOGITS   172032
#define OFF_MPART    237568
#define OFF_LPART    239104
#define OFF_ACCPART  240640
#define OFF_MFIN     1420288
#define OFF_LFIN     1420384
#define OFF_XFUSE    1420480
#define OFF_CTRL_LIN 1518784

// ---------------- helpers ----------------
__device__ __forceinline__ float block_sum256(float v, float* red) {
    int lane = threadIdx.x & 31, w = threadIdx.x >> 5;
#pragma unroll
    for (int o = 16; o; o >>= 1) v += __shfl_down_sync(0xffffffffu, v, o);
    if (lane == 0) red[w] = v;
    __syncthreads();
    if (w == 0) {
        float x = (lane < 8) ? red[lane] : 0.f;
#pragma unroll
        for (int o = 4; o; o >>= 1) x += __shfl_down_sync(0xffffffffu, x, o);
        if (lane == 0) red[0] = x;
    }
    __syncthreads();
    float r = red[0];
    __syncthreads();
    return r;
}

// ---------------- small GEMM: Out(rows,768) = X(rows,K) @ W(K,768) + bias ----------------
// grid (12 j-tiles of 64, rows/4 b-groups); 256 thr = 64 j x 4 k-strips.
// step_sel (device int*) optionally offsets W by step*K*768 and bias by step*768.
__global__ void k_gemm(const float* __restrict__ X, int K,
                       const float* __restrict__ W, const float* __restrict__ bias,
                       float* __restrict__ Out, const int* __restrict__ step_sel) {
    extern __shared__ float sm[];
    const int GB = 4;
    float* xs  = sm;            // GB*K
    float* red = sm + GB * K;   // 4*64*GB
    int jt = blockIdx.x, bt = blockIdx.y;
    int tid = threadIdx.x;
    int jl = tid & 63, strip = tid >> 6;
    int j = jt * 64 + jl;

    const float* Wb = W;
    const float* bb = bias;
    if (step_sel) {
        int st = *step_sel;
        Wb += (size_t)st * K * D;
        bb += (size_t)st * D;
    }
    for (int i = tid; i < GB * K; i += NTHR) {
        int r = i / K, k = i - r * K;
        xs[i] = X[(size_t)(bt * GB + r) * K + k];
    }
    __syncthreads();

    float acc[GB] = {0.f, 0.f, 0.f, 0.f};
    int k0 = strip * (K >> 2), k1 = k0 + (K >> 2);
    for (int k = k0; k < k1; k++) {
        float w = Wb[(size_t)k * D + j];
#pragma unroll
        for (int g = 0; g < GB; g++) acc[g] = fmaf(xs[g * K + k], w, acc[g]);
    }
#pragma unroll
    for (int g = 0; g < GB; g++) red[(strip * 64 + jl) * GB + g] = acc[g];
    __syncthreads();
    if (strip == 0) {
#pragma unroll
        for (int g = 0; g < GB; g++) {
            float v = red[jl * GB + g] + red[(64 + jl) * GB + g] +
                      red[(128 + jl) * GB + g] + red[(192 + jl) * GB + g];
            Out[(size_t)(bt * GB + g) * D + j] = v + bb[j];
        }
    }
}

// ---------------- LayerNorm + ReLU (rows = gridDim.x), optional elementwise mul ----------------
__global__ void k_ln_relu(const float* __restrict__ in, int in_stride,
                          float* __restrict__ out, int out_stride,
                          const float* __restrict__ g, const float* __restrict__ bv,
                          const float* __restrict__ wmul) {
    __shared__ float red[32];
    int r = blockIdx.x, tid = threadIdx.x;
    const float* x = in + (size_t)r * in_stride;
    float v[3];
#pragma unroll
    for (int i = 0; i < 3; i++) v[i] = x[tid + NTHR * i];
    float su = block_sum256(v[0] + v[1] + v[2], red);
    float mu = su * (1.f / D);
    float d0 = v[0] - mu, d1 = v[1] - mu, d2 = v[2] - mu;
    float ss = block_sum256(d0 * d0 + d1 * d1 + d2 * d2, red);
    float inv = rsqrtf(ss * (1.f / D) + 1e-5f);
#pragma unroll
    for (int i = 0; i < 3; i++) {
        int j = tid + NTHR * i;
        float y = (v[i] - mu) * inv * g[j] + bv[j];
        y = fmaxf(y, 0.f);
        if (wmul) y *= wmul[j];
        out[(size_t)r * out_stride + j] = y;
    }
}

// ---------------- concat [control | pa] -> xcq (32 x 2304) ----------------
__global__ void k_concat(const float* __restrict__ control, const float* __restrict__ pa,
                         float* __restrict__ xcq) {
    int idx = blockIdx.x * NTHR + threadIdx.x;  // 73728 total
    int b = idx / 2304, k = idx - b * 2304;
    xcq[idx] = (k < 1536) ? control[b * 1536 + k] : pa[b * D + (k - 1536)];
}

// ---------------- main pass: logits + 3-way online softmax weighted sums ----------------
// grid (b=32, chunk=16), 256 threads, ~102KB dyn smem
__global__ void k_main(const float* __restrict__ ctx, const float* __restrict__ qm1,
                       const float* __restrict__ qm2, const float* __restrict__ battn,
                       const float* __restrict__ u, float* __restrict__ logits,
                       float* __restrict__ mpart, float* __restrict__ lpart,
                       float* __restrict__ accpart) {
    extern __shared__ float sm[];
    float* ctx_sh  = sm;                 // TILE*D = 24576
    float* u_sh    = ctx_sh + TILE * D;  // 768
    float* dot_sh  = u_sh + D;           // 32
    float* pa_sh   = dot_sh + TILE;      // 3*32
    float* q1_sh   = pa_sh + 3 * TILE;   // 32
    float* q2_sh   = q1_sh + TILE;       // 32
    float* scale_sh = q2_sh + TILE;      // 4

    int b = blockIdx.x, ch = blockIdx.y;
    int tid = threadIdx.x;
    int w = tid >> 5, lane = tid & 31;

    for (int i = tid; i < D; i += NTHR) u_sh[i] = u[b * D + i];

    float acc[3][3];
#pragma unroll
    for (int t3 = 0; t3 < 3; t3++)
#pragma unroll
        for (int i = 0; i < 3; i++) acc[t3][i] = 0.f;

    float mold_r[3] = {-INFINITY, -INFINITY, -INFINITY};
    float l_r[3]    = {0.f, 0.f, 0.f};

    const float ba = battn[0];
    const float SC = 0.03608439182435161f;  // 1/sqrt(768)
    int s0 = ch * (NTILE * TILE);
    __syncthreads();

    for (int t = 0; t < NTILE; t++) {
        int sbase = s0 + t * TILE;
        // stage context tile (32 x 768) into smem, float4 coalesced
        {
            const float4* src = (const float4*)(ctx + ((size_t)b * SLEN + sbase) * D);
            float4* dst = (float4*)ctx_sh;
#pragma unroll
            for (int i = tid; i < TILE * D / 4; i += NTHR) dst[i] = src[i];
            if (tid < TILE) {
                q1_sh[tid] = qm1[b * SLEN + sbase + tid];
                q2_sh[tid] = qm2[b * SLEN + sbase + tid];
            }
        }
        __syncthreads();

        // dots: each warp handles 4 s-positions
#pragma unroll
        for (int q = 0; q < 4; q++) {
            int s = w * 4 + q;
            float a = 0.f;
#pragma unroll
            for (int i = 0; i < D / 32; i++) {
                int d = lane + 32 * i;
                a = fmaf(ctx_sh[s * D + d], u_sh[d], a);
            }
#pragma unroll
            for (int o = 16; o; o >>= 1) a += __shfl_down_sync(0xffffffffu, a, o);
            if (lane == 0) dot_sh[s] = a;
        }
        __syncthreads();

        // warp 0: logits, tile max/sum, online-softmax bookkeeping
        if (tid < 32) {
            int s = tid;
            float L = (dot_sh[s] + ba) * SC;
            logits[(size_t)b * SLEN + sbase + s] = L;
            float q1 = q1_sh[s], q2 = q2_sh[s];
            float lg[3];
            lg[0] = (q1 + q2) > 0.f ? L : -1e9f;
            lg[1] = q1 > 0.f ? L : -1e9f;
            lg[2] = q2 > 0.f ? L : -1e9f;
            float msk[3];
            msk[0] = 1.f;
            msk[1] = q1 > 0.f ? 1.f : 0.f;
            msk[2] = q2 > 0.f ? 1.f : 0.f;
#pragma unroll
            for (int t3 = 0; t3 < 3; t3++) {
                float mx = lg[t3];
#pragma unroll
                for (int o = 16; o; o >>= 1) mx = fmaxf(mx, __shfl_xor_sync(0xffffffffu, mx, o));
                float mnew = fmaxf(mold_r[t3], mx);
                float p = expf(lg[t3] - mnew);
                float psum = p;
#pragma unroll
                for (int o = 16; o; o >>= 1) psum += __shfl_xor_sync(0xffffffffu, psum, o);
                float sc = expf(mold_r[t3] - mnew);
                l_r[t3] = l_r[t3] * sc + psum;
                mold_r[t3] = mnew;
                pa_sh[t3 * TILE + s] = p * msk[t3];
                if (tid == 0) scale_sh[t3] = sc;
            }
        }
        __syncthreads();

        // accumulate: acc[t][d] = acc[t][d]*scale[t] + sum_s p_t[s]*ctx[s][d]
        float sc0 = scale_sh[0], sc1 = scale_sh[1], sc2 = scale_sh[2];
#pragma unroll
        for (int i = 0; i < 3; i++) {
            acc[0][i] *= sc0;
            acc[1][i] *= sc1;
            acc[2][i] *= sc2;
        }
        for (int s = 0; s < TILE; s++) {
            float p0 = pa_sh[0 * TILE + s];
            float p1 = pa_sh[1 * TILE + s];
            float p2 = pa_sh[2 * TILE + s];
#pragma unroll
            for (int i = 0; i < 3; i++) {
                float c = ctx_sh[s * D + tid + NTHR * i];
                acc[0][i] = fmaf(p0, c, acc[0][i]);
                acc[1][i] = fmaf(p1, c, acc[1][i]);
                acc[2][i] = fmaf(p2, c, acc[2][i]);
            }
        }
        __syncthreads();
    }

    // write partials
#pragma unroll
    for (int t3 = 0; t3 < 3; t3++) {
        size_t base = ((size_t)(b * CHUNKS + ch) * 3 + t3) * D;
#pragma unroll
        for (int i = 0; i < 3; i++) accpart[base + tid + NTHR * i] = acc[t3][i];
    }
    if (tid == 0) {
#pragma unroll
        for (int t3 = 0; t3 < 3; t3++) {
            mpart[(b * CHUNKS + ch) * 3 + t3] = mold_r[t3];
            lpart[(b * CHUNKS + ch) * 3 + t3] = l_r[t3];
        }
    }
}

// ---------------- combine partials, l2norm, build xfuse ----------------
// grid (b=32, t=3), 256 threads
__global__ void k_combine(const float* __restrict__ mpart, const float* __restrict__ lpart,
                          const float* __restrict__ accpart, float* __restrict__ mfin,
                          float* __restrict__ lfin, float* __restrict__ xfuse) {
    __shared__ float red[32];
    int b = blockIdx.x, t = blockIdx.y, tid = threadIdx.x;
    float m = -INFINITY;
#pragma unroll
    for (int c = 0; c < CHUNKS; c++) m = fmaxf(m, mpart[(b * CHUNKS + c) * 3 + t]);
    float l = 0.f;
    float v[3] = {0.f, 0.f, 0.f};
    for (int c = 0; c < CHUNKS; c++) {
        float wgt = expf(mpart[(b * CHUNKS + c) * 3 + t] - m);
        l += lpart[(b * CHUNKS + c) * 3 + t] * wgt;
        const float* ap = accpart + ((size_t)(b * CHUNKS + c) * 3 + t) * D;
#pragma unroll
        for (int i = 0; i < 3; i++) v[i] = fmaf(ap[tid + NTHR * i], wgt, v[i]);
    }
#pragma unroll
    for (int i = 0; i < 3; i++) v[i] /= l;
    float ss = block_sum256(v[0] * v[0] + v[1] * v[1] + v[2] * v[2], red);
    float inv = 1.f / fmaxf(sqrtf(ss), 1e-12f);
#pragma unroll
    for (int i = 0; i < 3; i++) v[i] *= inv;

    // t==0: ncf -> second halves of both fuse rows; t==1: mc1 -> row b; t==2: mc2 -> row 32+b
    if (t == 0) {
        float* d1 = xfuse + (size_t)b * 1536 + 768;
        float* d2 = xfuse + (size_t)(BATCH + b) * 1536 + 768;
#pragma unroll
        for (int i = 0; i < 3; i++) {
            d1[tid + NTHR * i] = v[i];
            d2[tid + NTHR * i] = v[i];
        }
    } else {
        float* d1 = (t == 1) ? (xfuse + (size_t)b * 1536) : (xfuse + (size_t)(BATCH + b) * 1536);
#pragma unroll
        for (int i = 0; i < 3; i++) d1[tid + NTHR * i] = v[i];
    }
    if (tid == 0) {
        mfin[b * 3 + t] = m;
        lfin[b * 3 + t] = l;
    }
}

// ---------------- attention map writer ----------------
__global__ void k_attn(const float* __restrict__ logits, const float* __restrict__ qm1,
                       const float* __restrict__ qm2, const float* __restrict__ mfin,
                       const float* __restrict__ lfin, float* __restrict__ out) {
    int idx = blockIdx.x * NTHR + threadIdx.x;  // 65536
    int b = idx >> 11, s = idx & (SLEN - 1);
    float L = logits[idx], q1 = qm1[idx], q2 = qm2[idx];
    float lg0 = (q1 + q2) > 0.f ? L : -1e9f;
    float lg1 = q1 > 0.f ? L : -1e9f;
    float lg2 = q2 > 0.f ? L : -1e9f;
    out[((size_t)b * 3 + 0) * SLEN + s] = expf(lg0 - mfin[b * 3 + 0]) / lfin[b * 3 + 0];
    out[((size_t)b * 3 + 1) * SLEN + s] = expf(lg1 - mfin[b * 3 + 1]) / lfin[b * 3 + 1];
    out[((size_t)b * 3 + 2) * SLEN + s] = expf(lg2 - mfin[b * 3 + 2]) / lfin[b * 3 + 2];
}

// ---------------- launch ----------------
extern "C" void kernel_launch(void* const* d_in, const int* in_sizes, int n_in,
                              void* d_out, int out_size) {
    const int*   step     = (const int*)d_in[0];
    const float* ctx      = (const float*)d_in[1];
    const float* question = (const float*)d_in[2];
    const float* control  = (const float*)d_in[3];
    const float* qm1      = (const float*)d_in[4];
    const float* qm2      = (const float*)d_in[5];
    const float* W_pos    = (const float*)d_in[8];
    const float* b_pos    = (const float*)d_in[9];
    const float* ln1_g    = (const float*)d_in[10];
    const float* ln1_b    = (const float*)d_in[11];
    const float* W_cq     = (const float*)d_in[12];
    const float* b_cq     = (const float*)d_in[13];
    const float* ln2_g    = (const float*)d_in[14];
    const float* ln2_b    = (const float*)d_in[15];
    const float* W_attn   = (const float*)d_in[16];
    const float* b_attn   = (const float*)d_in[17];
    const float* W_fuse   = (const float*)d_in[18];
    const float* b_fuse   = (const float*)d_in[19];
    const float* ln3_g    = (const float*)d_in[20];
    const float* ln3_b    = (const float*)d_in[21];
    const float* ln4_g    = (const float*)d_in[22];
    const float* ln4_b    = (const float*)d_in[23];
    float* out = (float*)d_out;

    void* sp = nullptr;
    cudaGetSymbolAddress(&sp, g_scratch);
    float* s = (float*)sp;

    const int mainSmem = (TILE * D + D + TILE + 3 * TILE + TILE + TILE + 4) * 4;  // ~102.2KB
    cudaFuncSetAttribute(k_main, cudaFuncAttributeMaxDynamicSharedMemorySize, mainSmem);

    // pa_lin = question @ W_pos[step] + b_pos[step]
    k_gemm<<<dim3(12, 8), NTHR, (4 * 768 + 1024) * 4>>>(question, 768, W_pos, b_pos,
                                                        s + OFF_PA_LIN, step);
    // pa = ln_relu(pa_lin)
    k_ln_relu<<<32, NTHR>>>(s + OFF_PA_LIN, 768, s + OFF_PA, 768, ln1_g, ln1_b, nullptr);
    // xcq = [control | pa]
    k_concat<<<288, NTHR>>>(control, s + OFF_PA, s + OFF_XCQ);
    // cq_lin = xcq @ W_cq + b_cq
    k_gemm<<<dim3(12, 8), NTHR, (4 * 2304 + 1024) * 4>>>(s + OFF_XCQ, 2304, W_cq, b_cq,
                                                         s + OFF_CQ_LIN, nullptr);
    // u = ln_relu(cq_lin) * W_attn
    k_ln_relu<<<32, NTHR>>>(s + OFF_CQ_LIN, 768, s + OFF_U, 768, ln2_g, ln2_b, W_attn);
    // main context pass
    k_main<<<dim3(BATCH, CHUNKS), NTHR, mainSmem>>>(ctx, qm1, qm2, b_attn, s + OFF_U,
                                                    s + OFF_LOGITS, s + OFF_MPART,
                                                    s + OFF_LPART, s + OFF_ACCPART);
    // combine partial softmax sums, l2norm, build xfuse
    k_combine<<<dim3(BATCH, 3), NTHR>>>(s + OFF_MPART, s + OFF_LPART, s + OFF_ACCPART,
                                        s + OFF_MFIN, s + OFF_LFIN, s + OFF_XFUSE);
    // ctrl_lin = xfuse @ W_fuse + b_fuse   (64 rows: ctrl1 then ctrl2)
    k_gemm<<<dim3(12, 16), NTHR, (4 * 1536 + 1024) * 4>>>(s + OFF_XFUSE, 1536, W_fuse, b_fuse,
                                                          s + OFF_CTRL_LIN, nullptr);
    // next_control halves
    k_ln_relu<<<32, NTHR>>>(s + OFF_CTRL_LIN, 768, out, 1536, ln3_g, ln3_b, nullptr);
    k_ln_relu<<<32, NTHR>>>(s + OFF_CTRL_LIN + 32 * 768, 768, out + 768, 1536, ln4_g, ln4_b,
                            nullptr);
    // attention maps
    k_attn<<<BATCH * SLEN / NTHR, NTHR>>>(s + OFF_LOGITS, qm1, qm2, s + OFF_MFIN, s + OFF_LFIN,
                                          out + BATCH * 1536);
}

// round 2
// speedup vs baseline: 1.7332x; 1.7332x over previous
#include <cuda_runtime.h>
#include <math.h>
#include <stdint.h>

#define D      768
#define SLEN   2048
#define BATCH  32
#define CHUNKS 16
#define TILE   32
#define NTILE  4
#define NTHR   256

// ---------------- scratch ----------------
// floats:
//   pa       [32*768]        @ 0
//   xcq      [32*2304]       @ 24576
//   u        [32*768]        @ 98304
//   logits   [32*2048]       @ 122880
//   mpart    [32*16*3]       @ 188416
//   lpart    [32*16*3]       @ 189952
//   accpart  [32*16*3*768]   @ 191488
//   mfin     [32*3]          @ 1371136
//   lfin     [32*3]          @ 1371232
//   xfuse    [64*1536]       @ 1371328
//   psum     [48*32*768]     @ 1469632   (1179648 floats, reused per gemm)
__device__ float g_scratch[2649600];

#define OFF_PA       0
#define OFF_XCQ      24576
#define OFF_U        98304
#define OFF_LOGITS   122880
#define OFF_MPART    188416
#define OFF_LPART    189952
#define OFF_ACCPART  191488
#define OFF_MFIN     1371136
#define OFF_LFIN     1371232
#define OFF_XFUSE    1371328
#define OFF_PSUM     1469632

// ---------------- helpers ----------------
__device__ __forceinline__ float block_sum256(float v, float* red) {
    int lane = threadIdx.x & 31, w = threadIdx.x >> 5;
#pragma unroll
    for (int o = 16; o; o >>= 1) v += __shfl_down_sync(0xffffffffu, v, o);
    if (lane == 0) red[w] = v;
    __syncthreads();
    if (w == 0) {
        float x = (lane < 8) ? red[lane] : 0.f;
#pragma unroll
        for (int o = 4; o; o >>= 1) x += __shfl_down_sync(0xffffffffu, x, o);
        if (lane == 0) red[0] = x;
    }
    __syncthreads();
    float r = red[0];
    __syncthreads();
    return r;
}

// ---------------- weight-streaming split-K GEMM ----------------
// psum[kslice][rg*32 + r][j] = sum_{k in slice} X[r][k] * W[k][j]
// grid: (3 j-tiles of 256, K/KS k-slices, rows/32 row-groups), 256 threads.
// W streamed once, coalesced, k-unrolled x4 for MLP.
template <int KS>
__global__ void k_gemm_stream(const float* __restrict__ X, int K,
                              const float* __restrict__ W, float* __restrict__ psum,
                              const int* __restrict__ step_sel, int rows_tot) {
    __shared__ float xs[32 * KS];
    int tid = threadIdx.x;
    int j = blockIdx.x * 256 + tid;
    int k0 = blockIdx.y * KS;
    int rg = blockIdx.z;

    const float* Wb = W;
    if (step_sel) Wb += (size_t)(*step_sel) * K * D;
    const float* Xb = X + (size_t)rg * 32 * K;

    for (int i = tid; i < 32 * KS; i += 256) {
        int r = i / KS, kk = i - r * KS;
        xs[i] = Xb[(size_t)r * K + k0 + kk];
    }
    __syncthreads();

    float acc[32];
#pragma unroll
    for (int r = 0; r < 32; r++) acc[r] = 0.f;

#pragma unroll 4
    for (int kk = 0; kk < KS; kk++) {
        float w = Wb[(size_t)(k0 + kk) * D + j];
#pragma unroll
        for (int r = 0; r < 32; r++) acc[r] = fmaf(xs[r * KS + kk], w, acc[r]);
    }

    float* ps = psum + ((size_t)blockIdx.y * rows_tot + rg * 32) * D + j;
#pragma unroll
    for (int r = 0; r < 32; r++) ps[(size_t)r * D] = acc[r];
}

// ---------------- split-K reduce + bias + LayerNorm + ReLU (+ optional mul) ----------------
// one CTA per output row (gridDim.x rows); psum row index = row0 + blockIdx.x
__global__ void k_ln_relu2(const float* __restrict__ psum, int nslices, int sstride, int row0,
                           const float* __restrict__ bias, const int* __restrict__ step_sel,
                           float* __restrict__ out, int out_stride,
                           const float* __restrict__ g, const float* __restrict__ bv,
                           const float* __restrict__ wmul) {
    __shared__ float red[32];
    int r = row0 + blockIdx.x, tid = threadIdx.x;
    const float* bb = bias;
    if (step_sel) bb += (size_t)(*step_sel) * D;

    float v[3];
#pragma unroll
    for (int i = 0; i < 3; i++) {
        int j = tid + NTHR * i;
        float a = bb[j];
        const float* p = psum + (size_t)r * D + j;
#pragma unroll 4
        for (int c = 0; c < nslices; c++) a += p[(size_t)c * sstride];
        v[i] = a;
    }
    float su = block_sum256(v[0] + v[1] + v[2], red);
    float mu = su * (1.f / D);
    float d0 = v[0] - mu, d1 = v[1] - mu, d2 = v[2] - mu;
    float ss = block_sum256(d0 * d0 + d1 * d1 + d2 * d2, red);
    float inv = rsqrtf(ss * (1.f / D) + 1e-5f);
#pragma unroll
    for (int i = 0; i < 3; i++) {
        int j = tid + NTHR * i;
        float y = (v[i] - mu) * inv * g[j] + bv[j];
        y = fmaxf(y, 0.f);
        if (wmul) y *= wmul[j];
        out[(size_t)blockIdx.x * out_stride + j] = y;
    }
}

// ---------------- concat [control | pa] -> xcq (32 x 2304) ----------------
__global__ void k_concat(const float* __restrict__ control, const float* __restrict__ pa,
                         float* __restrict__ xcq) {
    int idx = blockIdx.x * NTHR + threadIdx.x;
    int b = idx / 2304, k = idx - b * 2304;
    xcq[idx] = (k < 1536) ? control[b * 1536 + k] : pa[b * D + (k - 1536)];
}

// ---------------- main pass: logits + 3-way online softmax weighted sums ----------------
__global__ void k_main(const float* __restrict__ ctx, const float* __restrict__ qm1,
                       const float* __restrict__ qm2, const float* __restrict__ battn,
                       const float* __restrict__ u, float* __restrict__ logits,
                       float* __restrict__ mpart, float* __restrict__ lpart,
                       float* __restrict__ accpart) {
    extern __shared__ float sm[];
    float* ctx_sh   = sm;
    float* u_sh     = ctx_sh + TILE * D;
    float* dot_sh   = u_sh + D;
    float* pa_sh    = dot_sh + TILE;
    float* q1_sh    = pa_sh + 3 * TILE;
    float* q2_sh    = q1_sh + TILE;
    float* scale_sh = q2_sh + TILE;

    int b = blockIdx.x, ch = blockIdx.y;
    int tid = threadIdx.x;
    int w = tid >> 5, lane = tid & 31;

    for (int i = tid; i < D; i += NTHR) u_sh[i] = u[b * D + i];

    float acc[3][3];
#pragma unroll
    for (int t3 = 0; t3 < 3; t3++)
#pragma unroll
        for (int i = 0; i < 3; i++) acc[t3][i] = 0.f;

    float mold_r[3] = {-INFINITY, -INFINITY, -INFINITY};
    float l_r[3]    = {0.f, 0.f, 0.f};

    const float ba = battn[0];
    const float SC = 0.03608439182435161f;
    int s0 = ch * (NTILE * TILE);
    __syncthreads();

    for (int t = 0; t < NTILE; t++) {
        int sbase = s0 + t * TILE;
        {
            const float4* src = (const float4*)(ctx + ((size_t)b * SLEN + sbase) * D);
            float4* dst = (float4*)ctx_sh;
#pragma unroll
            for (int i = tid; i < TILE * D / 4; i += NTHR) dst[i] = src[i];
            if (tid < TILE) {
                q1_sh[tid] = qm1[b * SLEN + sbase + tid];
                q2_sh[tid] = qm2[b * SLEN + sbase + tid];
            }
        }
        __syncthreads();

#pragma unroll
        for (int q = 0; q < 4; q++) {
            int s = w * 4 + q;
            float a = 0.f;
#pragma unroll
            for (int i = 0; i < D / 32; i++) {
                int d = lane + 32 * i;
                a = fmaf(ctx_sh[s * D + d], u_sh[d], a);
            }
#pragma unroll
            for (int o = 16; o; o >>= 1) a += __shfl_down_sync(0xffffffffu, a, o);
            if (lane == 0) dot_sh[s] = a;
        }
        __syncthreads();

        if (tid < 32) {
            int s = tid;
            float L = (dot_sh[s] + ba) * SC;
            logits[(size_t)b * SLEN + sbase + s] = L;
            float q1 = q1_sh[s], q2 = q2_sh[s];
            float lg[3];
            lg[0] = (q1 + q2) > 0.f ? L : -1e9f;
            lg[1] = q1 > 0.f ? L : -1e9f;
            lg[2] = q2 > 0.f ? L : -1e9f;
            float msk[3];
            msk[0] = 1.f;
            msk[1] = q1 > 0.f ? 1.f : 0.f;
            msk[2] = q2 > 0.f ? 1.f : 0.f;
#pragma unroll
            for (int t3 = 0; t3 < 3; t3++) {
                float mx = lg[t3];
#pragma unroll
                for (int o = 16; o; o >>= 1) mx = fmaxf(mx, __shfl_xor_sync(0xffffffffu, mx, o));
                float mnew = fmaxf(mold_r[t3], mx);
                float p = expf(lg[t3] - mnew);
                float psumv = p;
#pragma unroll
                for (int o = 16; o; o >>= 1) psumv += __shfl_xor_sync(0xffffffffu, psumv, o);
                float sc = expf(mold_r[t3] - mnew);
                l_r[t3] = l_r[t3] * sc + psumv;
                mold_r[t3] = mnew;
                pa_sh[t3 * TILE + s] = p * msk[t3];
                if (tid == 0) scale_sh[t3] = sc;
            }
        }
        __syncthreads();

        float sc0 = scale_sh[0], sc1 = scale_sh[1], sc2 = scale_sh[2];
#pragma unroll
        for (int i = 0; i < 3; i++) {
            acc[0][i] *= sc0;
            acc[1][i] *= sc1;
            acc[2][i] *= sc2;
        }
        for (int s = 0; s < TILE; s++) {
            float p0 = pa_sh[0 * TILE + s];
            float p1 = pa_sh[1 * TILE + s];
            float p2 = pa_sh[2 * TILE + s];
#pragma unroll
            for (int i = 0; i < 3; i++) {
                float c = ctx_sh[s * D + tid + NTHR * i];
                acc[0][i] = fmaf(p0, c, acc[0][i]);
                acc[1][i] = fmaf(p1, c, acc[1][i]);
                acc[2][i] = fmaf(p2, c, acc[2][i]);
            }
        }
        __syncthreads();
    }

#pragma unroll
    for (int t3 = 0; t3 < 3; t3++) {
        size_t base = ((size_t)(b * CHUNKS + ch) * 3 + t3) * D;
#pragma unroll
        for (int i = 0; i < 3; i++) accpart[base + tid + NTHR * i] = acc[t3][i];
    }
    if (tid == 0) {
#pragma unroll
        for (int t3 = 0; t3 < 3; t3++) {
            mpart[(b * CHUNKS + ch) * 3 + t3] = mold_r[t3];
            lpart[(b * CHUNKS + ch) * 3 + t3] = l_r[t3];
        }
    }
}

// ---------------- combine partials, l2norm, build xfuse ----------------
__global__ void k_combine(const float* __restrict__ mpart, const float* __restrict__ lpart,
                          const float* __restrict__ accpart, float* __restrict__ mfin,
                          float* __restrict__ lfin, float* __restrict__ xfuse) {
    __shared__ float red[32];
    int b = blockIdx.x, t = blockIdx.y, tid = threadIdx.x;
    float m = -INFINITY;
#pragma unroll
    for (int c = 0; c < CHUNKS; c++) m = fmaxf(m, mpart[(b * CHUNKS + c) * 3 + t]);
    float l = 0.f;
    float v[3] = {0.f, 0.f, 0.f};
    for (int c = 0; c < CHUNKS; c++) {
        float wgt = expf(mpart[(b * CHUNKS + c) * 3 + t] - m);
        l += lpart[(b * CHUNKS + c) * 3 + t] * wgt;
        const float* ap = accpart + ((size_t)(b * CHUNKS + c) * 3 + t) * D;
#pragma unroll
        for (int i = 0; i < 3; i++) v[i] = fmaf(ap[tid + NTHR * i], wgt, v[i]);
    }
#pragma unroll
    for (int i = 0; i < 3; i++) v[i] /= l;
    float ss = block_sum256(v[0] * v[0] + v[1] * v[1] + v[2] * v[2], red);
    float inv = 1.f / fmaxf(sqrtf(ss), 1e-12f);
#pragma unroll
    for (int i = 0; i < 3; i++) v[i] *= inv;

    if (t == 0) {
        float* d1 = xfuse + (size_t)b * 1536 + 768;
        float* d2 = xfuse + (size_t)(BATCH + b) * 1536 + 768;
#pragma unroll
        for (int i = 0; i < 3; i++) {
            d1[tid + NTHR * i] = v[i];
            d2[tid + NTHR * i] = v[i];
        }
    } else {
        float* d1 = (t == 1) ? (xfuse + (size_t)b * 1536) : (xfuse + (size_t)(BATCH + b) * 1536);
#pragma unroll
        for (int i = 0; i < 3; i++) d1[tid + NTHR * i] = v[i];
    }
    if (tid == 0) {
        mfin[b * 3 + t] = m;
        lfin[b * 3 + t] = l;
    }
}

// ---------------- attention map writer ----------------
__global__ void k_attn(const float* __restrict__ logits, const float* __restrict__ qm1,
                       const float* __restrict__ qm2, const float* __restrict__ mfin,
                       const float* __restrict__ lfin, float* __restrict__ out) {
    int idx = blockIdx.x * NTHR + threadIdx.x;
    int b = idx >> 11, s = idx & (SLEN - 1);
    float L = logits[idx], q1 = qm1[idx], q2 = qm2[idx];
    float lg0 = (q1 + q2) > 0.f ? L : -1e9f;
    float lg1 = q1 > 0.f ? L : -1e9f;
    float lg2 = q2 > 0.f ? L : -1e9f;
    out[((size_t)b * 3 + 0) * SLEN + s] = expf(lg0 - mfin[b * 3 + 0]) / lfin[b * 3 + 0];
    out[((size_t)b * 3 + 1) * SLEN + s] = expf(lg1 - mfin[b * 3 + 1]) / lfin[b * 3 + 1];
    out[((size_t)b * 3 + 2) * SLEN + s] = expf(lg2 - mfin[b * 3 + 2]) / lfin[b * 3 + 2];
}

// ---------------- launch ----------------
extern "C" void kernel_launch(void* const* d_in, const int* in_sizes, int n_in,
                              void* d_out, int out_size) {
    const int*   step     = (const int*)d_in[0];
    const float* ctx      = (const float*)d_in[1];
    const float* question = (const float*)d_in[2];
    const float* control  = (const float*)d_in[3];
    const float* qm1      = (const float*)d_in[4];
    const float* qm2      = (const float*)d_in[5];
    const float* W_pos    = (const float*)d_in[8];
    const float* b_pos    = (const float*)d_in[9];
    const float* ln1_g    = (const float*)d_in[10];
    const float* ln1_b    = (const float*)d_in[11];
    const float* W_cq     = (const float*)d_in[12];
    const float* b_cq     = (const float*)d_in[13];
    const float* ln2_g    = (const float*)d_in[14];
    const float* ln2_b    = (const float*)d_in[15];
    const float* W_attn   = (const float*)d_in[16];
    const float* b_attn   = (const float*)d_in[17];
    const float* W_fuse   = (const float*)d_in[18];
    const float* b_fuse   = (const float*)d_in[19];
    const float* ln3_g    = (const float*)d_in[20];
    const float* ln3_b    = (const float*)d_in[21];
    const float* ln4_g    = (const float*)d_in[22];
    const float* ln4_b    = (const float*)d_in[23];
    float* out = (float*)d_out;

    void* sp = nullptr;
    cudaGetSymbolAddress(&sp, g_scratch);
    float* s = (float*)sp;

    const int mainSmem = (TILE * D + D + TILE + 3 * TILE + TILE + TILE + 4) * 4;
    cudaFuncSetAttribute(k_main, cudaFuncAttributeMaxDynamicSharedMemorySize, mainSmem);

    // pa = ln_relu(question @ W_pos[step] + b_pos[step])
    k_gemm_stream<32><<<dim3(3, 24, 1), NTHR>>>(question, 768, W_pos, s + OFF_PSUM, step, 32);
    k_ln_relu2<<<32, NTHR>>>(s + OFF_PSUM, 24, 32 * D, 0, b_pos, step, s + OFF_PA, D,
                             ln1_g, ln1_b, nullptr);
    // xcq = [control | pa]
    k_concat<<<288, NTHR>>>(control, s + OFF_PA, s + OFF_XCQ);
    // u = ln_relu(xcq @ W_cq + b_cq) * W_attn
    k_gemm_stream<48><<<dim3(3, 48, 1), NTHR>>>(s + OFF_XCQ, 2304, W_cq, s + OFF_PSUM,
                                                nullptr, 32);
    k_ln_relu2<<<32, NTHR>>>(s + OFF_PSUM, 48, 32 * D, 0, b_cq, nullptr, s + OFF_U, D,
                             ln2_g, ln2_b, W_attn);
    // main context pass
    k_main<<<dim3(BATCH, CHUNKS), NTHR, mainSmem>>>(ctx, qm1, qm2, b_attn, s + OFF_U,
                                                    s + OFF_LOGITS, s + OFF_MPART,
                                                    s + OFF_LPART, s + OFF_ACCPART);
    // combine
    k_combine<<<dim3(BATCH, 3), NTHR>>>(s + OFF_MPART, s + OFF_LPART, s + OFF_ACCPART,
                                        s + OFF_MFIN, s + OFF_LFIN, s + OFF_XFUSE);
    // ctrl1/ctrl2 = ln_relu(xfuse @ W_fuse + b_fuse)
    k_gemm_stream<64><<<dim3(3, 24, 2), NTHR>>>(s + OFF_XFUSE, 1536, W_fuse, s + OFF_PSUM,
                                                nullptr, 64);
    k_ln_relu2<<<32, NTHR>>>(s + OFF_PSUM, 24, 64 * D, 0, b_fuse, nullptr, out, 1536,
                             ln3_g, ln3_b, nullptr);
    k_ln_relu2<<<32, NTHR>>>(s + OFF_PSUM, 24, 64 * D, 32, b_fuse, nullptr, out + 768, 1536,
                             ln4_g, ln4_b, nullptr);
    // attention maps
    k_attn<<<BATCH * SLEN / NTHR, NTHR>>>(s + OFF_LOGITS, qm1, qm2, s + OFF_MFIN, s + OFF_LFIN,
                                          out + BATCH * 1536);
}

// round 3
// speedup vs baseline: 2.6664x; 1.5384x over previous
#include <cuda_runtime.h>
#include <math.h>
#include <stdint.h>

#define D      768
#define SLEN   2048
#define BATCH  32
#define CHUNKS 8
#define TILE   32
#define NTILE  8
#define NTHR   256

// ---------------- scratch ----------------
__device__ float g_scratch[1600000];
#define OFF_PA       0        // 32*768
#define OFF_U        24576    // 32*768
#define OFF_LOGITS   49152    // 32*2048
#define OFF_MPART    114688   // 32*8*3
#define OFF_LPART    115456   // 32*8*3
#define OFF_ACCPART  116224   // 32*8*3*768 = 589824
#define OFF_MFIN     706048   // 96
#define OFF_LFIN     706144   // 96
#define OFF_XFUSE    706240   // 64*1536
#define OFF_PSUM     804544   // up to 786432

// ---------------- f32x2 helpers ----------------
__device__ __forceinline__ unsigned long long pack2(float lo, float hi) {
    unsigned long long r;
    asm("mov.b64 %0,{%1,%2};" : "=l"(r) : "f"(lo), "f"(hi));
    return r;
}
__device__ __forceinline__ void unpack2(unsigned long long v, float& lo, float& hi) {
    asm("mov.b64 {%0,%1},%2;" : "=f"(lo), "=f"(hi) : "l"(v));
}
__device__ __forceinline__ void fma2(unsigned long long& d, unsigned long long a,
                                     unsigned long long b) {
    asm("fma.rn.f32x2 %0,%1,%2,%0;" : "+l"(d) : "l"(a), "l"(b));
}
__device__ __forceinline__ void mul2(unsigned long long& d, unsigned long long a) {
    asm("mul.rn.f32x2 %0,%0,%1;" : "+l"(d) : "l"(a));
}

// ---------------- reductions ----------------
__device__ __forceinline__ float block_sum256(float v, float* red) {
    int lane = threadIdx.x & 31, w = threadIdx.x >> 5;
#pragma unroll
    for (int o = 16; o; o >>= 1) v += __shfl_down_sync(0xffffffffu, v, o);
    if (lane == 0) red[w] = v;
    __syncthreads();
    if (w == 0) {
        float x = (lane < 8) ? red[lane] : 0.f;
#pragma unroll
        for (int o = 4; o; o >>= 1) x += __shfl_down_sync(0xffffffffu, x, o);
        if (lane == 0) red[0] = x;
    }
    __syncthreads();
    float r = red[0];
    __syncthreads();
    return r;
}

__device__ __forceinline__ float block_sum768(float v, float* red) {
    int lane = threadIdx.x & 31, w = threadIdx.x >> 5;
#pragma unroll
    for (int o = 16; o; o >>= 1) v += __shfl_down_sync(0xffffffffu, v, o);
    if (lane == 0) red[w] = v;
    __syncthreads();
    if (w == 0) {
        float x = (lane < 24) ? red[lane] : 0.f;
#pragma unroll
        for (int o = 16; o; o >>= 1) x += __shfl_down_sync(0xffffffffu, x, o);
        if (lane == 0) red[0] = x;
    }
    __syncthreads();
    float r = red[0];
    __syncthreads();
    return r;
}

// ---------------- weight-streaming split-K GEMM (f32x2) ----------------
// X logical row r col k = (k<K1)? X1[r*s1+k] : X2[r*s2+k-K1]
// psum[(slice*rows_tot + r)*768 + j]
template <int KS, int RACC>
__global__ void k_gemm2(const float* __restrict__ X1, int K1, int s1,
                        const float* __restrict__ X2, int s2,
                        const float* __restrict__ W, int K,
                        float* __restrict__ psum, const int* __restrict__ step_sel,
                        int rows_tot) {
    __shared__ __align__(16) float xs[KS * RACC];  // transposed: [kk][r]
    int tid = threadIdx.x;
    int j = blockIdx.x * 256 + tid;
    int k0 = blockIdx.y * KS;
    int r0 = blockIdx.z * RACC;

    const float* Wb = W;
    if (step_sel) Wb += (size_t)(*step_sel) * K * D;

    for (int i = tid; i < KS * RACC; i += 256) {
        int r = i / KS, kk = i - r * KS;
        int k = k0 + kk;
        float v = (k < K1) ? X1[(size_t)(r0 + r) * s1 + k]
                           : X2[(size_t)(r0 + r) * s2 + (k - K1)];
        xs[kk * RACC + r] = v;
    }
    __syncthreads();

    unsigned long long acc2[RACC / 2];
#pragma unroll
    for (int p = 0; p < RACC / 2; p++) acc2[p] = 0ull;

    for (int kk0 = 0; kk0 < KS; kk0 += 8) {
        float w[8];
#pragma unroll
        for (int u = 0; u < 8; u++) w[u] = Wb[(size_t)(k0 + kk0 + u) * D + j];
#pragma unroll
        for (int u = 0; u < 8; u++) {
            unsigned long long w2 = pack2(w[u], w[u]);
            const float4* xr = (const float4*)(xs + (kk0 + u) * RACC);
#pragma unroll
            for (int p = 0; p < RACC / 4; p++) {
                float4 xv = xr[p];
                fma2(acc2[2 * p], pack2(xv.x, xv.y), w2);
                fma2(acc2[2 * p + 1], pack2(xv.z, xv.w), w2);
            }
        }
    }

    float* ps = psum + ((size_t)blockIdx.y * rows_tot + r0) * D + j;
#pragma unroll
    for (int p = 0; p < RACC / 2; p++) {
        float lo, hi;
        unpack2(acc2[p], lo, hi);
        ps[(size_t)(2 * p) * D] = lo;
        ps[(size_t)(2 * p + 1) * D] = hi;
    }
}

// ---------------- slice-reduce + bias + LN + ReLU (+mul / fuse split-write) ----------------
// 768 threads, one CTA per row.
__global__ void k_reduce_ln(const float* __restrict__ psum, int nslices, int rows_tot,
                            const float* __restrict__ bias, const int* __restrict__ step_sel,
                            float* __restrict__ out,
                            const float* __restrict__ g1, const float* __restrict__ b1,
                            const float* __restrict__ g2, const float* __restrict__ b2,
                            const float* __restrict__ wmul, int fuse_map) {
    __shared__ float red[32];
    int r = blockIdx.x, tid = threadIdx.x;
    const float* bb = bias;
    if (step_sel) bb += (size_t)(*step_sel) * D;

    float a = bb[tid];
    const float* p = psum + (size_t)r * D + tid;
    size_t stride = (size_t)rows_tot * D;
#pragma unroll 4
    for (int c = 0; c < nslices; c++) a += p[(size_t)c * stride];

    float su = block_sum768(a, red);
    float mu = su * (1.f / D);
    float dd = a - mu;
    float ss = block_sum768(dd * dd, red);
    float inv = rsqrtf(ss * (1.f / D) + 1e-5f);

    const float* g = g1;
    const float* bv = b1;
    float* dst;
    if (fuse_map) {
        int half = r >> 5, bidx = r & 31;
        dst = out + (size_t)bidx * 1536 + half * 768;
        if (half) { g = g2; bv = b2; }
    } else {
        dst = out + (size_t)r * D;
    }
    float y = fmaxf(dd * inv * g[tid] + bv[tid], 0.f);
    if (wmul) y *= wmul[tid];
    dst[tid] = y;
}

// ---------------- main pass: logits + 3-way online softmax weighted sums ----------------
// grid (32, 8), 256 threads, single 96KB ctx buffer, cp.async staging, 2 CTAs/SM.
__global__ void k_main(const float* __restrict__ ctx, const float* __restrict__ qm1,
                       const float* __restrict__ qm2, const float* __restrict__ battn,
                       const float* __restrict__ u, float* __restrict__ logits,
                       float* __restrict__ mpart, float* __restrict__ lpart,
                       float* __restrict__ accpart) {
    extern __shared__ __align__(16) float sm[];
    float* ctx_sh   = sm;          // 24576
    float* dot_sh   = sm + 24576;  // 32
    float* pa_sh    = sm + 24608;  // 96
    float* q1_sh    = sm + 24704;  // 32
    float* q2_sh    = sm + 24736;  // 32
    float* scale_sh = sm + 24768;  // 4

    int b = blockIdx.x, ch = blockIdx.y;
    int tid = threadIdx.x;
    int w = tid >> 5, lane = tid & 31;

    float u_reg[24];
    {
        const float* ub = u + (size_t)b * D;
#pragma unroll
        for (int i = 0; i < 24; i++) u_reg[i] = ub[lane + 32 * i];
    }

    unsigned long long acc2[3][2];
#pragma unroll
    for (int t3 = 0; t3 < 3; t3++) { acc2[t3][0] = 0ull; acc2[t3][1] = 0ull; }

    float m_r = -INFINITY, l_r = 0.f;  // online state for warps 0-2 (per type)
    const float ba = battn[0];
    const float SC = 0.03608439182435161f;  // 1/sqrt(768)

    uint32_t ctx_sa = (uint32_t)__cvta_generic_to_shared(ctx_sh);
    uint32_t q1_sa  = (uint32_t)__cvta_generic_to_shared(q1_sh);
    uint32_t q2_sa  = (uint32_t)__cvta_generic_to_shared(q2_sh);

    for (int t = 0; t < NTILE; t++) {
        int sbase = ch * (NTILE * TILE) + t * TILE;
        const float4* src = (const float4*)(ctx + ((size_t)b * SLEN + sbase) * D);
#pragma unroll
        for (int i = 0; i < (TILE * D / 4) / NTHR; i++) {
            int idx = tid + NTHR * i;
            asm volatile("cp.async.cg.shared.global [%0],[%1],16;"
                         :: "r"(ctx_sa + idx * 16), "l"(src + idx));
        }
        if (tid < 32) {
            asm volatile("cp.async.ca.shared.global [%0],[%1],4;"
                         :: "r"(q1_sa + tid * 4), "l"(qm1 + (size_t)b * SLEN + sbase + tid));
        } else if (tid < 64) {
            asm volatile("cp.async.ca.shared.global [%0],[%1],4;"
                         :: "r"(q2_sa + (tid - 32) * 4),
                            "l"(qm2 + (size_t)b * SLEN + sbase + (tid - 32)));
        }
        asm volatile("cp.async.commit_group;");
        asm volatile("cp.async.wait_group 0;");
        __syncthreads();

        // dots: warp w handles s = 4w..4w+3
#pragma unroll
        for (int q = 0; q < 4; q++) {
            int s = w * 4 + q;
            const float* cp = ctx_sh + s * D;
            float a0 = 0.f, a1 = 0.f;
#pragma unroll
            for (int i = 0; i < 24; i += 2) {
                a0 = fmaf(cp[lane + 32 * i], u_reg[i], a0);
                a1 = fmaf(cp[lane + 32 * (i + 1)], u_reg[i + 1], a1);
            }
            float a = a0 + a1;
#pragma unroll
            for (int o = 16; o; o >>= 1) a += __shfl_down_sync(0xffffffffu, a, o);
            if (lane == 0) dot_sh[s] = a;
        }
        __syncthreads();

        // softmax bookkeeping: warp w<3 handles type w; warp 3 writes logits
        if (w < 3) {
            float L = (dot_sh[lane] + ba) * SC;
            float q1 = q1_sh[lane], q2 = q2_sh[lane];
            float qv = (w == 0) ? (q1 + q2) : ((w == 1) ? q1 : q2);
            float lg = (qv > 0.f) ? L : -1e9f;
            float msk = (w == 0) ? 1.f : ((qv > 0.f) ? 1.f : 0.f);
            float mx = lg;
#pragma unroll
            for (int o = 16; o; o >>= 1) mx = fmaxf(mx, __shfl_xor_sync(0xffffffffu, mx, o));
            float mnew = fmaxf(m_r, mx);
            float p = expf(lg - mnew);
            float psv = p;
#pragma unroll
            for (int o = 16; o; o >>= 1) psv += __shfl_xor_sync(0xffffffffu, psv, o);
            float sc = expf(m_r - mnew);
            l_r = l_r * sc + psv;
            m_r = mnew;
            pa_sh[w * 32 + lane] = p * msk;
            if (lane == 0) scale_sh[w] = sc;
        } else if (w == 3) {
            logits[(size_t)b * SLEN + sbase + lane] = (dot_sh[lane] + ba) * SC;
        }
        __syncthreads();

        // accumulate: 192 threads x 4 consecutive cols, f32x2 FMAs
        if (tid < 192) {
            unsigned long long s20 = pack2(scale_sh[0], scale_sh[0]);
            unsigned long long s21 = pack2(scale_sh[1], scale_sh[1]);
            unsigned long long s22 = pack2(scale_sh[2], scale_sh[2]);
            mul2(acc2[0][0], s20); mul2(acc2[0][1], s20);
            mul2(acc2[1][0], s21); mul2(acc2[1][1], s21);
            mul2(acc2[2][0], s22); mul2(acc2[2][1], s22);
            const float4* cb = (const float4*)ctx_sh + tid;
#pragma unroll 4
            for (int s = 0; s < TILE; s++) {
                float4 c = cb[s * (D / 4)];
                unsigned long long c01 = pack2(c.x, c.y);
                unsigned long long c23 = pack2(c.z, c.w);
                unsigned long long p0 = pack2(pa_sh[s], pa_sh[s]);
                unsigned long long p1 = pack2(pa_sh[32 + s], pa_sh[32 + s]);
                unsigned long long p2 = pack2(pa_sh[64 + s], pa_sh[64 + s]);
                fma2(acc2[0][0], c01, p0); fma2(acc2[0][1], c23, p0);
                fma2(acc2[1][0], c01, p1); fma2(acc2[1][1], c23, p1);
                fma2(acc2[2][0], c01, p2); fma2(acc2[2][1], c23, p2);
            }
        }
        __syncthreads();
    }

    if (tid < 192) {
#pragma unroll
        for (int t3 = 0; t3 < 3; t3++) {
            float4 o;
            unpack2(acc2[t3][0], o.x, o.y);
            unpack2(acc2[t3][1], o.z, o.w);
            ((float4*)(accpart + ((size_t)(b * CHUNKS + ch) * 3 + t3) * D))[tid] = o;
        }
    }
    if (w < 3 && lane == 0) {
        mpart[(b * CHUNKS + ch) * 3 + w] = m_r;
        lpart[(b * CHUNKS + ch) * 3 + w] = l_r;
    }
}

// ---------------- combine partials, l2norm, build xfuse ----------------
__global__ void k_combine(const float* __restrict__ mpart, const float* __restrict__ lpart,
                          const float* __restrict__ accpart, float* __restrict__ mfin,
                          float* __restrict__ lfin, float* __restrict__ xfuse) {
    __shared__ float red[32];
    int b = blockIdx.x, t = blockIdx.y, tid = threadIdx.x;
    float m = -INFINITY;
#pragma unroll
    for (int c = 0; c < CHUNKS; c++) m = fmaxf(m, mpart[(b * CHUNKS + c) * 3 + t]);
    float l = 0.f;
    float v[3] = {0.f, 0.f, 0.f};
    for (int c = 0; c < CHUNKS; c++) {
        float wgt = expf(mpart[(b * CHUNKS + c) * 3 + t] - m);
        l += lpart[(b * CHUNKS + c) * 3 + t] * wgt;
        const float* ap = accpart + ((size_t)(b * CHUNKS + c) * 3 + t) * D;
#pragma unroll
        for (int i = 0; i < 3; i++) v[i] = fmaf(ap[tid + NTHR * i], wgt, v[i]);
    }
#pragma unroll
    for (int i = 0; i < 3; i++) v[i] /= l;
    float ss = block_sum256(v[0] * v[0] + v[1] * v[1] + v[2] * v[2], red);
    float inv = 1.f / fmaxf(sqrtf(ss), 1e-12f);
#pragma unroll
    for (int i = 0; i < 3; i++) v[i] *= inv;

    if (t == 0) {
        float* d1 = xfuse + (size_t)b * 1536 + 768;
        float* d2 = xfuse + (size_t)(BATCH + b) * 1536 + 768;
#pragma unroll
        for (int i = 0; i < 3; i++) {
            d1[tid + NTHR * i] = v[i];
            d2[tid + NTHR * i] = v[i];
        }
    } else {
        float* d1 = (t == 1) ? (xfuse + (size_t)b * 1536) : (xfuse + (size_t)(BATCH + b) * 1536);
#pragma unroll
        for (int i = 0; i < 3; i++) d1[tid + NTHR * i] = v[i];
    }
    if (tid == 0) {
        mfin[b * 3 + t] = m;
        lfin[b * 3 + t] = l;
    }
}

// ---------------- attention map writer ----------------
__global__ void k_attn(const float* __restrict__ logits, const float* __restrict__ qm1,
                       const float* __restrict__ qm2, const float* __restrict__ mfin,
                       const float* __restrict__ lfin, float* __restrict__ out) {
    int idx = blockIdx.x * NTHR + threadIdx.x;
    int b = idx >> 11, s = idx & (SLEN - 1);
    float L = logits[idx], q1 = qm1[idx], q2 = qm2[idx];
    float lg0 = (q1 + q2) > 0.f ? L : -1e9f;
    float lg1 = q1 > 0.f ? L : -1e9f;
    float lg2 = q2 > 0.f ? L : -1e9f;
    out[((size_t)b * 3 + 0) * SLEN + s] = expf(lg0 - mfin[b * 3 + 0]) / lfin[b * 3 + 0];
    out[((size_t)b * 3 + 1) * SLEN + s] = expf(lg1 - mfin[b * 3 + 1]) / lfin[b * 3 + 1];
    out[((size_t)b * 3 + 2) * SLEN + s] = expf(lg2 - mfin[b * 3 + 2]) / lfin[b * 3 + 2];
}

// ---------------- launch ----------------
extern "C" void kernel_launch(void* const* d_in, const int* in_sizes, int n_in,
                              void* d_out, int out_size) {
    const int*   step     = (const int*)d_in[0];
    const float* ctx      = (const float*)d_in[1];
    const float* question = (const float*)d_in[2];
    const float* control  = (const float*)d_in[3];
    const float* qm1      = (const float*)d_in[4];
    const float* qm2      = (const float*)d_in[5];
    const float* W_pos    = (const float*)d_in[8];
    const float* b_pos    = (const float*)d_in[9];
    const float* ln1_g    = (const float*)d_in[10];
    const float* ln1_b    = (const float*)d_in[11];
    const float* W_cq     = (const float*)d_in[12];
    const float* b_cq     = (const float*)d_in[13];
    const float* ln2_g    = (const float*)d_in[14];
    const float* ln2_b    = (const float*)d_in[15];
    const float* W_attn   = (const float*)d_in[16];
    const float* b_attn   = (const float*)d_in[17];
    const float* W_fuse   = (const float*)d_in[18];
    const float* b_fuse   = (const float*)d_in[19];
    const float* ln3_g    = (const float*)d_in[20];
    const float* ln3_b    = (const float*)d_in[21];
    const float* ln4_g    = (const float*)d_in[22];
    const float* ln4_b    = (const float*)d_in[23];
    float* out = (float*)d_out;

    void* sp = nullptr;
    cudaGetSymbolAddress(&sp, g_scratch);
    float* s = (float*)sp;

    const int mainSmem = 24772 * 4;
    cudaFuncSetAttribute(k_main, cudaFuncAttributeMaxDynamicSharedMemorySize, mainSmem);

    // pa = ln_relu(question @ W_pos[step] + b_pos[step])
    k_gemm2<32, 16><<<dim3(3, 24, 2), NTHR>>>(question, 768, 768, nullptr, 0, W_pos, 768,
                                              s + OFF_PSUM, step, 32);
    k_reduce_ln<<<32, 768>>>(s + OFF_PSUM, 24, 32, b_pos, step, s + OFF_PA,
                             ln1_g, ln1_b, nullptr, nullptr, nullptr, 0);
    // u = ln_relu([control|pa] @ W_cq + b_cq) * W_attn
    k_gemm2<96, 16><<<dim3(3, 24, 2), NTHR>>>(control, 1536, 1536, s + OFF_PA, 768, W_cq, 2304,
                                              s + OFF_PSUM, nullptr, 32);
    k_reduce_ln<<<32, 768>>>(s + OFF_PSUM, 24, 32, b_cq, nullptr, s + OFF_U,
                             ln2_g, ln2_b, nullptr, nullptr, W_attn, 0);
    // main context pass
    k_main<<<dim3(BATCH, CHUNKS), NTHR, mainSmem>>>(ctx, qm1, qm2, b_attn, s + OFF_U,
                                                    s + OFF_LOGITS, s + OFF_MPART,
                                                    s + OFF_LPART, s + OFF_ACCPART);
    // combine
    k_combine<<<dim3(BATCH, 3), NTHR>>>(s + OFF_MPART, s + OFF_LPART, s + OFF_ACCPART,
                                        s + OFF_MFIN, s + OFF_LFIN, s + OFF_XFUSE);
    // ctrl1/ctrl2 = ln_relu(xfuse @ W_fuse + b_fuse) written straight to out
    k_gemm2<96, 16><<<dim3(3, 16, 4), NTHR>>>(s + OFF_XFUSE, 1536, 1536, nullptr, 0, W_fuse,
                                              1536, s + OFF_PSUM, nullptr, 64);
    k_reduce_ln<<<64, 768>>>(s + OFF_PSUM, 16, 64, b_fuse, nullptr, out,
                             ln3_g, ln3_b, ln4_g, ln4_b, nullptr, 1);
    // attention maps
    k_attn<<<BATCH * SLEN / NTHR, NTHR>>>(s + OFF_LOGITS, qm1, qm2, s + OFF_MFIN, s + OFF_LFIN,
                                          out + BATCH * 1536);
}